// round 7
// baseline (speedup 1.0000x reference)
#include <cuda_runtime.h>
#include <cuda_bf16.h>
#include <math.h>

typedef __nv_bfloat16 bf16;
typedef __nv_bfloat162 bf162;

// Problem constants
#define BB   32
#define NN_  4096
#define PP   256
#define DX_  128
#define DU_  64
#define DK_  128
#define DV_  128
#define DOUT_ 256
#define HH   512
#define TOK  (BB*NN_)   // 131072
#define BPQ  (BB*PP)    // 8192
#define KSPLIT 8

// ---------------- arena (separate hi/lo bf16 planes per buffer) --------------
// plane sizes in halves
#define PL_XU   25165824ull   /* TOK*192 */
#define PL_H    67108864ull   /* TOK*512 */
#define PL_S    33554432ull   /* BB*PP*NN_ */
#define PL_KV   16777216ull   /* TOK*128 */
#define PL_W    1146880ull
#define PL_Q    1048576ull    /* BPQ*128 */

#define OFF_XU  0ull
#define OFF_H1  100663296ull
#define OFF_H2  369098752ull
#define OFF_SS  OFF_H2                 /* Ss aliases h2 (dead after Vt GEMM) */
#define OFF_KS  637534208ull
#define OFF_VT  704643072ull
#define OFF_PT  771751936ull
#define OFF_WS  805306368ull
#define OFF_Q   809893888ull
#define OFF_QS  814088192ull
#define OFF_PL  818282496ull
#define OFF_DQ  822476800ull
#define OFF_LW  826671104ull
#define ARENA_BYTES 827195392ull

__device__ __align__(1024) char g_arena[ARENA_BYTES];

// transposed weight plane offsets (halves)
#define WOFF_KW1 0u
#define WOFF_KW2 65536u
#define WOFF_KW3 327680u
#define WOFF_VW1 393216u
#define WOFF_VW2 491520u
#define WOFF_VW3 753664u
#define WOFF_RW1 819200u
#define WOFF_RW2 884736u
#define WOFF_FW1 1015808u
#define WOFF_FW2 1081344u

// ---------------- helpers ----------------------------------------------------
__device__ __forceinline__ float gelu_tanh(float x) {
    float x3 = x*x*x;
    return 0.5f*x*(1.0f + tanhf(0.7978845608028654f*(x + 0.044715f*x3)));
}
__device__ __forceinline__ float warp_sum(float v) {
#pragma unroll
    for (int o = 16; o > 0; o >>= 1) v += __shfl_xor_sync(0xffffffffu, v, o);
    return v;
}
__device__ __forceinline__ float warp_max(float v) {
#pragma unroll
    for (int o = 16; o > 0; o >>= 1) v = fmaxf(v, __shfl_xor_sync(0xffffffffu, v, o));
    return v;
}
__device__ __forceinline__ void store_one(bf16* ph, bf16* pl, size_t off, float v) {
    bf16 h = __float2bfloat16(v);
    float f = __bfloat162float(h);
    float r = (fabsf(f) <= 3.38e38f) ? v - f : 0.f;
    ph[off] = h;
    pl[off] = __float2bfloat16(r);
}
__device__ __forceinline__ void store_pair(bf16* ph, bf16* pl, size_t off, float v0, float v1) {
    bf16 h0 = __float2bfloat16(v0), h1 = __float2bfloat16(v1);
    float f0 = __bfloat162float(h0), f1 = __bfloat162float(h1);
    float r0 = (fabsf(f0) <= 3.38e38f) ? v0 - f0 : 0.f;
    float r1 = (fabsf(f1) <= 3.38e38f) ? v1 - f1 : 0.f;
    bf162 hv; hv.x = h0; hv.y = h1;
    bf162 lv; lv.x = __float2bfloat16(r0); lv.y = __float2bfloat16(r1);
    *(bf162*)(ph + off) = hv;
    *(bf162*)(pl + off) = lv;
}
__device__ __forceinline__ void mma_bf16(float d[4], const unsigned a[4], const unsigned b[2]) {
    asm volatile(
        "mma.sync.aligned.m16n8k16.row.col.f32.bf16.bf16.f32 "
        "{%0,%1,%2,%3}, {%4,%5,%6,%7}, {%8,%9}, {%0,%1,%2,%3};\n"
        : "+f"(d[0]), "+f"(d[1]), "+f"(d[2]), "+f"(d[3])
        : "r"(a[0]), "r"(a[1]), "r"(a[2]), "r"(a[3]), "r"(b[0]), "r"(b[1]));
}
__device__ __forceinline__ void ldsm4(unsigned r[4], unsigned addr) {
    asm volatile("ldmatrix.sync.aligned.m8n8.x4.shared.b16 {%0,%1,%2,%3}, [%4];"
        : "=r"(r[0]), "=r"(r[1]), "=r"(r[2]), "=r"(r[3]) : "r"(addr));
}
__device__ __forceinline__ unsigned smem_u32(const void* p) {
    return (unsigned)__cvta_generic_to_shared(p);
}
__device__ __forceinline__ void cp16(unsigned dst, const void* src) {
    asm volatile("cp.async.cg.shared.global [%0], [%1], 16;\n" :: "r"(dst), "l"(src));
}

// smem geometry (units = halves).  BK = 32 k-values per tile.
#define AST  40                     /* row stride: 32 + 8 pad; ldmatrix conflict-free */
#define ABUF (128*AST)              /* 5120 halves per plane per buffer */
#define SMEM_BYTES (8*ABUF*2)       /* A(2buf*2pl) + B(2buf*2pl) = 81920 B */

// =============================================================================
// 3xBF16 NT tensor-core GEMM core on separate hi/lo planes.
// C[128 x 128] tile += A[M,K](lda) @ B[N,K](ldb)^T.  256 thr, warps 2m x 4n.
// Fragments loaded with ldmatrix.x4 (zero PRMT in inner loop).
// =============================================================================
__device__ __forceinline__ void tc_core(
    const bf16* __restrict__ Ah, const bf16* __restrict__ Al, int lda,
    const bf16* __restrict__ Bh, const bf16* __restrict__ Bl, int ldb,
    int K, int bm, int bn, float (&acc)[4][4][4], bf16* sA, bf16* sB)
{
    const int tid = threadIdx.x, lane = tid & 31;
    const int warp = tid >> 5;
    const int m0 = (warp >> 2) * 64, n0 = (warp & 3) * 32;

    auto issue = [&](int k0, int buf) {
        const int po = buf * 2 * ABUF;
#pragma unroll
        for (int i = 0; i < 2; i++) {
            int idx = tid + i * 256;
            int r = idx >> 2, c = (idx & 3) * 8;
            cp16(smem_u32(sA + po + r * AST + c),        Ah + (size_t)(bm + r) * lda + k0 + c);
            cp16(smem_u32(sA + po + ABUF + r * AST + c), Al + (size_t)(bm + r) * lda + k0 + c);
            cp16(smem_u32(sB + po + r * AST + c),        Bh + (size_t)(bn + r) * ldb + k0 + c);
            cp16(smem_u32(sB + po + ABUF + r * AST + c), Bl + (size_t)(bn + r) * ldb + k0 + c);
        }
        asm volatile("cp.async.commit_group;\n");
    };

    // ldmatrix per-lane base offsets (bytes within one plane buffer)
    const unsigned aLane = ((m0 + (lane & 7) + ((lane >> 3) & 1) * 8) * AST + (lane >> 4) * 8) * 2;
    const unsigned bLane = ((n0 + (lane & 7) + (lane >> 4) * 8) * AST + ((lane >> 3) & 1) * 8) * 2;
    const unsigned uA = smem_u32(sA) + aLane;
    const unsigned uB = smem_u32(sB) + bLane;

    const int nt = K >> 5;
    issue(0, 0);
    for (int t = 0; t < nt; t++) {
        const int buf = t & 1;
        if (t + 1 < nt) { issue((t + 1) << 5, buf ^ 1); asm volatile("cp.async.wait_group 1;\n"); }
        else            { asm volatile("cp.async.wait_group 0;\n"); }
        __syncthreads();
        const unsigned aB = uA + buf * (2 * ABUF * 2);
        const unsigned bB = uB + buf * (2 * ABUF * 2);
#pragma unroll
        for (int kk = 0; kk < 32; kk += 16) {
            unsigned bh[4][2], bl[4][2];
#pragma unroll
            for (int np = 0; np < 2; np++) {
                unsigned r[4];
                ldsm4(r, bB + (np * 16 * AST + kk) * 2);
                bh[2*np][0] = r[0]; bh[2*np][1] = r[1];
                bh[2*np+1][0] = r[2]; bh[2*np+1][1] = r[3];
                ldsm4(r, bB + (ABUF + np * 16 * AST + kk) * 2);
                bl[2*np][0] = r[0]; bl[2*np][1] = r[1];
                bl[2*np+1][0] = r[2]; bl[2*np+1][1] = r[3];
            }
#pragma unroll
            for (int mi = 0; mi < 4; mi++) {
                unsigned ah[4], al[4];
                ldsm4(ah, aB + (mi * 16 * AST + kk) * 2);
                ldsm4(al, aB + (ABUF + mi * 16 * AST + kk) * 2);
#pragma unroll
                for (int ni = 0; ni < 4; ni++) {
                    mma_bf16(acc[mi][ni], al, bh[ni]);
                    mma_bf16(acc[mi][ni], ah, bl[ni]);
                    mma_bf16(acc[mi][ni], ah, bh[ni]);
                }
            }
        }
        __syncthreads();
    }
}

// EPI: 1 +bias(col) | 2 gelu(+bias col) | 3 *scale+logw(col, per-z) | 4 +bias(row)
// SOUT: write hi/lo planes; else fp32.
template<int EPI, bool SOUT>
__global__ __launch_bounds__(256, 2)
void gemm_nt(const bf16* __restrict__ A, const bf16* __restrict__ B,
             const float* __restrict__ aux, float* __restrict__ C,
             bf16* __restrict__ Ch,
             int N, int K, int lda, int ldb, int ldc, float scale,
             size_t planeA, size_t planeB, size_t planeC,
             size_t sA_, size_t sB_, size_t sC_, size_t sAux)
{
    extern __shared__ bf16 smu[];
    bf16* sA = smu;
    bf16* sB = smu + 4 * ABUF;
    const int bm = blockIdx.y * 128, bn = blockIdx.x * 128, z = blockIdx.z;

    float acc[4][4][4];
#pragma unroll
    for (int a = 0; a < 4; a++)
#pragma unroll
        for (int b = 0; b < 4; b++)
#pragma unroll
            for (int c = 0; c < 4; c++) acc[a][b][c] = 0.f;

    const bf16* Azh = A + (size_t)z * sA_;
    const bf16* Bzh = B + (size_t)z * sB_;
    tc_core(Azh, Azh + planeA, lda, Bzh, Bzh + planeB, ldb, K, bm, bn, acc, sA, sB);

    const int tid = threadIdx.x, lane = tid & 31, warp = tid >> 5;
    const int g = lane >> 2, t4 = lane & 3;
    const int m0 = (warp >> 2) * 64, n0 = (warp & 3) * 32;
    const float* ax = aux + (size_t)z * sAux;
    bf16* Czh = SOUT ? Ch + (size_t)z * sC_ : nullptr;
    bf16* Czl = SOUT ? Czh + planeC : nullptr;
    float* Cz = SOUT ? nullptr : C + (size_t)z * sC_;
#pragma unroll
    for (int mi = 0; mi < 4; mi++) {
#pragma unroll
        for (int ni = 0; ni < 4; ni++) {
            int col = bn + n0 + ni * 8 + 2 * t4;
#pragma unroll
            for (int h = 0; h < 2; h++) {
                int row = bm + m0 + mi * 16 + g + h * 8;
                float v0 = acc[mi][ni][2 * h], v1 = acc[mi][ni][2 * h + 1];
                if (EPI == 1) { v0 += ax[col]; v1 += ax[col + 1]; }
                if (EPI == 2) { v0 = gelu_tanh(v0 + ax[col]); v1 = gelu_tanh(v1 + ax[col + 1]); }
                if (EPI == 3) { v0 = v0 * scale + ax[col]; v1 = v1 * scale + ax[col + 1]; }
                if (EPI == 4) { v0 += ax[row]; v1 += ax[row]; }
                if (SOUT) store_pair(Czh, Czl, (size_t)row * ldc + col, v0, v1);
                else *(float2*)(Cz + (size_t)row * ldc + col) = make_float2(v0, v1);
            }
        }
    }
}

// ---------------- split-K GEMM for pooled = probs @ Vt^T (fp32 partials) -----
__global__ __launch_bounds__(256, 2)
void gemm_avk(const bf16* __restrict__ Sh, const bf16* __restrict__ Vth,
              float* __restrict__ Pt, size_t planeS, size_t planeV)
{
    extern __shared__ bf16 smu[];
    bf16* sA = smu;
    bf16* sB = smu + 4 * ABUF;
    const int bz = blockIdx.z;
    const int b = bz >> 3, kc = bz & (KSPLIT - 1);
    const int KC = NN_ / KSPLIT; // 512
    const bf16* A = Sh + (size_t)b * PP * NN_ + (size_t)kc * KC;
    const bf16* B = Vth + (size_t)b * NN_ + (size_t)kc * KC;
    const int bm = blockIdx.y * 128;

    float acc[4][4][4];
#pragma unroll
    for (int a = 0; a < 4; a++)
#pragma unroll
        for (int bb = 0; bb < 4; bb++)
#pragma unroll
            for (int c = 0; c < 4; c++) acc[a][bb][c] = 0.f;

    tc_core(A, A + planeS, NN_, B, B + planeV, TOK, KC, bm, 0, acc, sA, sB);

    const int tid = threadIdx.x, lane = tid & 31, warp = tid >> 5;
    const int g = lane >> 2, t4 = lane & 3;
    const int m0 = (warp >> 2) * 64, n0 = (warp & 3) * 32;
    float* c0 = Pt + (size_t)bz * PP * DV_;
#pragma unroll
    for (int mi = 0; mi < 4; mi++)
#pragma unroll
        for (int ni = 0; ni < 4; ni++) {
            int col = n0 + ni * 8 + 2 * t4;
#pragma unroll
            for (int h = 0; h < 2; h++) {
                int row = bm + m0 + mi * 16 + g + h * 8;
                *(float2*)(c0 + (size_t)row * DV_ + col) =
                    make_float2(acc[mi][ni][2 * h], acc[mi][ni][2 * h + 1]);
            }
        }
}

__global__ __launch_bounds__(256)
void reduce_avk(const float* __restrict__ Pt, bf16* __restrict__ ph, bf16* __restrict__ pl)
{
    const size_t total = (size_t)BB * PP * DV_;
    size_t i = (size_t)blockIdx.x * 256 + threadIdx.x;
    if (i >= total) return;
    size_t b = i / ((size_t)PP * DV_);
    size_t r = i - b * (size_t)PP * DV_;
    const float* p = Pt + b * KSPLIT * (size_t)PP * DV_ + r;
    float s = 0.f;
#pragma unroll
    for (int kc = 0; kc < KSPLIT; kc++) s += p[(size_t)kc * PP * DV_];
    store_one(ph, pl, i, s);
}

// ---------------- softmax over 4096-wide rows, in-place on planes ------------
__global__ __launch_bounds__(256)
void softmax4096(bf16* __restrict__ Sh, bf16* __restrict__ Sl)
{
    const size_t base = (size_t)blockIdx.x * NN_;
    bf16* sh = Sh + base;
    bf16* sl = Sl + base;
    const int t = threadIdx.x;
    const int w = t >> 5, lane = t & 31;
    __shared__ float red[8];

    float v[16];
    float mx = -INFINITY;
#pragma unroll
    for (int i = 0; i < 16; i++) {
        int idx = t + i * 256;
        v[i] = __bfloat162float(sh[idx]) + __bfloat162float(sl[idx]);
        mx = fmaxf(mx, v[i]);
    }
    mx = warp_max(mx);
    if (lane == 0) red[w] = mx;
    __syncthreads();
    mx = red[0];
#pragma unroll
    for (int i = 1; i < 8; i++) mx = fmaxf(mx, red[i]);
    __syncthreads();

    float sum = 0.f;
#pragma unroll
    for (int i = 0; i < 16; i++) { v[i] = __expf(v[i] - mx); sum += v[i]; }
    sum = warp_sum(sum);
    if (lane == 0) red[w] = sum;
    __syncthreads();
    float tot = 0.f;
#pragma unroll
    for (int i = 0; i < 8; i++) tot += red[i];
    float inv = 1.0f / tot;
#pragma unroll
    for (int i = 0; i < 16; i++) store_one(sh, sl, t + i * 256, v[i] * inv);
}

// ---------------- Q = LayerNorm(Q + dQ); emits fp32 + planes -----------------
__global__ __launch_bounds__(128)
void add_layernorm(float* __restrict__ Q, bf16* __restrict__ Qh, bf16* __restrict__ Ql,
                   const float* __restrict__ dQ,
                   const float* __restrict__ g, const float* __restrict__ b)
{
    const int row = blockIdx.x, t = threadIdx.x;
    const size_t idx = (size_t)row * DK_ + t;
    const int w = t >> 5, lane = t & 31;
    __shared__ float sh[4];

    float x = Q[idx] + dQ[idx];
    float s = warp_sum(x);
    if (lane == 0) sh[w] = s;
    __syncthreads();
    float mean = (sh[0] + sh[1] + sh[2] + sh[3]) * (1.0f / DK_);
    float d = x - mean;
    __syncthreads();
    float s2 = warp_sum(d * d);
    if (lane == 0) sh[w] = s2;
    __syncthreads();
    float var = (sh[0] + sh[1] + sh[2] + sh[3]) * (1.0f / DK_);
    float y = d * rsqrtf(var + 1e-5f) * g[t] + b[t];
    Q[idx] = y;
    store_one(Qh, Ql, idx, y);
}

// ---------------- prep kernels -----------------------------------------------
__global__ void prep_logw(const void* __restrict__ mask, const float* __restrict__ sw,
                          float* __restrict__ lw, int n)
{
    const unsigned int w0 = *(const unsigned int*)mask;
    const int mode = (w0 == 0x3F800000u) ? 2 : ((w0 == 1u) ? 1 : 0);
    int i = blockIdx.x * blockDim.x + threadIdx.x;
    if (i >= n) return;
    bool on;
    if (mode == 1)      on = ((const int*)mask)[i] != 0;
    else if (mode == 2) on = ((const float*)mask)[i] != 0.f;
    else                on = ((const unsigned char*)mask)[i] != 0;
    lw[i] = on ? logf(fmaxf(sw[i], 1e-8f)) : -INFINITY;
}

// pack transposed weight: dst[o][i] = w[i][o], hi/lo planes
__global__ void packw(const float* __restrict__ w, bf16* __restrict__ dh,
                      bf16* __restrict__ dl, int fin, int fout)
{
    int total = fin * fout;
    for (int idx = blockIdx.x * blockDim.x + threadIdx.x; idx < total;
         idx += gridDim.x * blockDim.x) {
        int o = idx / fin, i = idx - o * fin;
        store_one(dh, dl, idx, w[(size_t)i * fout + o]);
    }
}

__global__ void concat_xu(const float* __restrict__ x, const float* __restrict__ u,
                          bf16* __restrict__ xh, bf16* __restrict__ xl)
{
    const size_t total = (size_t)TOK * (DX_ + DU_);
    for (size_t i = (size_t)blockIdx.x * blockDim.x + threadIdx.x; i < total;
         i += (size_t)gridDim.x * blockDim.x) {
        size_t tkn = i / (DX_ + DU_);
        int c = (int)(i - tkn * (DX_ + DU_));
        float v = (c < DX_) ? x[tkn * DX_ + c] : u[tkn * DU_ + (c - DX_)];
        store_one(xh, xl, i, v);
    }
}

__global__ void bcast_q(const float* __restrict__ qt, float* __restrict__ Q,
                        bf16* __restrict__ Qh, bf16* __restrict__ Ql)
{
    const size_t total = (size_t)BPQ * DK_;
    const size_t per = (size_t)PP * DK_;
    for (size_t i = (size_t)blockIdx.x * blockDim.x + threadIdx.x; i < total;
         i += (size_t)gridDim.x * blockDim.x) {
        float v = qt[i % per];
        Q[i] = v;
        store_one(Qh, Ql, i, v);
    }
}

// ---------------- host launcher ----------------------------------------------
extern "C" void kernel_launch(void* const* d_in, const int* in_sizes, int n_in,
                              void* d_out, int out_size)
{
    const float* x_enc = (const float*)d_in[0];
    const float* u     = (const float*)d_in[1];
    const void*  mask  = d_in[2];
    const float* sw    = (const float*)d_in[3];
    const float* k_w1 = (const float*)d_in[4];  const float* k_b1 = (const float*)d_in[5];
    const float* k_w2 = (const float*)d_in[6];  const float* k_b2 = (const float*)d_in[7];
    const float* k_w3 = (const float*)d_in[8];  const float* k_b3 = (const float*)d_in[9];
    const float* v_w1 = (const float*)d_in[10]; const float* v_b1 = (const float*)d_in[11];
    const float* v_w2 = (const float*)d_in[12]; const float* v_b2 = (const float*)d_in[13];
    const float* v_w3 = (const float*)d_in[14]; const float* v_b3 = (const float*)d_in[15];
    const float* qtok = (const float*)d_in[16];
    const float* rho_w1 = (const float*)d_in[17]; const float* rho_b1 = (const float*)d_in[18];
    const float* rho_w2 = (const float*)d_in[19]; const float* rho_b2 = (const float*)d_in[20];
    const float* ref_w1 = (const float*)d_in[21]; const float* ref_b1 = (const float*)d_in[22];
    const float* ref_w2 = (const float*)d_in[23]; const float* ref_b2 = (const float*)d_in[24];
    const float* ln_g = (const float*)d_in[25];   const float* ln_b = (const float*)d_in[26];
    float* out = (float*)d_out;

    char* arena;
    cudaGetSymbolAddress((void**)&arena, g_arena);
    bf16* xuh  = (bf16*)(arena + OFF_XU);
    bf16* h1h  = (bf16*)(arena + OFF_H1);
    bf16* h2h  = (bf16*)(arena + OFF_H2);
    bf16* Ssh  = (bf16*)(arena + OFF_SS);   // aliases h2
    bf16* Ksh  = (bf16*)(arena + OFF_KS);
    bf16* Vth  = (bf16*)(arena + OFF_VT);
    float* pt  = (float*)(arena + OFF_PT);
    bf16* wsh  = (bf16*)(arena + OFF_WS);
    float* Q   = (float*)(arena + OFF_Q);
    bf16* Qsh  = (bf16*)(arena + OFF_QS);
    bf16* plh  = (bf16*)(arena + OFF_PL);
    float* dQ  = (float*)(arena + OFF_DQ);
    float* lw  = (float*)(arena + OFF_LW);

    cudaFuncSetAttribute(gemm_nt<1,true>,  cudaFuncAttributeMaxDynamicSharedMemorySize, SMEM_BYTES);
    cudaFuncSetAttribute(gemm_nt<1,false>, cudaFuncAttributeMaxDynamicSharedMemorySize, SMEM_BYTES);
    cudaFuncSetAttribute(gemm_nt<2,true>,  cudaFuncAttributeMaxDynamicSharedMemorySize, SMEM_BYTES);
    cudaFuncSetAttribute(gemm_nt<3,true>,  cudaFuncAttributeMaxDynamicSharedMemorySize, SMEM_BYTES);
    cudaFuncSetAttribute(gemm_nt<4,true>,  cudaFuncAttributeMaxDynamicSharedMemorySize, SMEM_BYTES);
    cudaFuncSetAttribute(gemm_avk,         cudaFuncAttributeMaxDynamicSharedMemorySize, SMEM_BYTES);

    const float scale = 0.08838834764831843f; // 1/sqrt(128)

    // prep + one-shot packs (weights transposed)
    prep_logw<<<(TOK + 255) / 256, 256>>>(mask, sw, lw, TOK);
    concat_xu<<<4096, 256>>>(x_enc, u, xuh, xuh + PL_XU);
    bcast_q<<<1024, 256>>>(qtok, Q, Qsh, Qsh + PL_Q);
    bf16* wsl = wsh + PL_W;
    packw<<<256, 256>>>(k_w1, wsh + WOFF_KW1, wsl + WOFF_KW1, DX_, HH);
    packw<<<512, 256>>>(k_w2, wsh + WOFF_KW2, wsl + WOFF_KW2, HH, HH);
    packw<<<256, 256>>>(k_w3, wsh + WOFF_KW3, wsl + WOFF_KW3, HH, DK_);
    packw<<<256, 256>>>(v_w1, wsh + WOFF_VW1, wsl + WOFF_VW1, DX_+DU_, HH);
    packw<<<512, 256>>>(v_w2, wsh + WOFF_VW2, wsl + WOFF_VW2, HH, HH);
    packw<<<256, 256>>>(v_w3, wsh + WOFF_VW3, wsl + WOFF_VW3, HH, DV_);
    packw<<<256, 256>>>(rho_w1, wsh + WOFF_RW1, wsl + WOFF_RW1, DV_, HH);
    packw<<<256, 256>>>(rho_w2, wsh + WOFF_RW2, wsl + WOFF_RW2, HH, DOUT_);
    packw<<<256, 256>>>(ref_w1, wsh + WOFF_FW1, wsl + WOFF_FW1, DV_, HH);
    packw<<<256, 256>>>(ref_w2, wsh + WOFF_FW2, wsl + WOFF_FW2, HH, DK_);

    // K = mlp3(x_enc); layer 1 reads x-half of xu (lda = 192)
    gemm_nt<2,true><<<dim3(4,1024,1), 256, SMEM_BYTES>>>(
        xuh, wsh + WOFF_KW1, k_b1, nullptr, h1h,
        HH, DX_, DX_+DU_, DX_, HH, 0.f, PL_XU, PL_W, PL_H, 0,0,0,0);
    gemm_nt<2,true><<<dim3(4,1024,1), 256, SMEM_BYTES>>>(
        h1h, wsh + WOFF_KW2, k_b2, nullptr, h2h,
        HH, HH, HH, HH, HH, 0.f, PL_H, PL_W, PL_H, 0,0,0,0);
    gemm_nt<1,true><<<dim3(1,1024,1), 256, SMEM_BYTES>>>(
        h2h, wsh + WOFF_KW3, k_b3, nullptr, Ksh,
        DK_, HH, HH, HH, DK_, 0.f, PL_H, PL_W, PL_KV, 0,0,0,0);

    // V = mlp3([x|u]); layer 3 produced TRANSPOSED: Vt = w3T @ h2^T  [128 x TOK]
    gemm_nt<2,true><<<dim3(4,1024,1), 256, SMEM_BYTES>>>(
        xuh, wsh + WOFF_VW1, v_b1, nullptr, h1h,
        HH, DX_+DU_, DX_+DU_, DX_+DU_, HH, 0.f, PL_XU, PL_W, PL_H, 0,0,0,0);
    gemm_nt<2,true><<<dim3(4,1024,1), 256, SMEM_BYTES>>>(
        h1h, wsh + WOFF_VW2, v_b2, nullptr, h2h,
        HH, HH, HH, HH, HH, 0.f, PL_H, PL_W, PL_H, 0,0,0,0);
    gemm_nt<4,true><<<dim3(1024,1,1), 256, SMEM_BYTES>>>(
        wsh + WOFF_VW3, h2h, v_b3, nullptr, Vth,
        TOK, HH, HH, HH, TOK, 0.f, PL_W, PL_H, PL_KV, 0,0,0,0);

    // attention + refinement (3 iterations).  Ss aliases h2 (dead after Vt).
    for (int iter = 0; iter < 3; iter++) {
        gemm_nt<3,true><<<dim3(32,2,BB), 256, SMEM_BYTES>>>(
            Qsh, Ksh, lw, nullptr, Ssh,
            NN_, DK_, DK_, DK_, NN_, scale, PL_Q, PL_KV, PL_S,
            (size_t)PP*DK_, (size_t)NN_*DK_, (size_t)PP*NN_, (size_t)NN_);
        softmax4096<<<BB*PP, 256>>>(Ssh, Ssh + PL_S);
        gemm_avk<<<dim3(1,2,BB*KSPLIT), 256, SMEM_BYTES>>>(Ssh, Vth, pt, PL_S, PL_KV);
        reduce_avk<<<(BB*PP*DV_ + 255)/256, 256>>>(pt, plh, plh + PL_Q);
        if (iter < 2) {
            gemm_nt<2,true><<<dim3(4,64,1), 256, SMEM_BYTES>>>(
                plh, wsh + WOFF_FW1, ref_b1, nullptr, h1h,
                HH, DV_, DV_, DV_, HH, 0.f, PL_Q, PL_W, PL_H, 0,0,0,0);
            gemm_nt<1,false><<<dim3(1,64,1), 256, SMEM_BYTES>>>(
                h1h, wsh + WOFF_FW2, ref_b2, dQ, nullptr,
                DK_, HH, HH, HH, DK_, 0.f, PL_H, PL_W, 0, 0,0,0,0);
            add_layernorm<<<BPQ, 128>>>(Q, Qsh, Qsh + PL_Q, dQ, ln_g, ln_b);
        }
    }

    // out = mlp2(pooled)
    gemm_nt<2,true><<<dim3(4,64,1), 256, SMEM_BYTES>>>(
        plh, wsh + WOFF_RW1, rho_b1, nullptr, h1h,
        HH, DV_, DV_, DV_, HH, 0.f, PL_Q, PL_W, PL_H, 0,0,0,0);
    gemm_nt<1,false><<<dim3(2,64,1), 256, SMEM_BYTES>>>(
        h1h, wsh + WOFF_RW2, rho_b2, out, nullptr,
        DOUT_, HH, HH, HH, DOUT_, 0.f, PL_H, PL_W, 0, 0,0,0,0);

    (void)in_sizes; (void)n_in; (void)out_size;
}